// round 1
// baseline (speedup 1.0000x reference)
#include <cuda_runtime.h>
#include <cstdint>
#include <cstddef>

// MotherNetRegression fused forward:
//   out[t,b] = relu(x[t,b,:] @ W1[b] + b1[b]) @ w2[b] + b2[b]
// T=4096, B=8, F=512, H=1024, O=1
//
// Strategy (round 0): fused SIMT kernel using packed fp32x2 FMA
// (fma.rn.f32x2, 2x the 3-reg FFMA rate on Blackwell). Block computes a
// 64(t) x 64(h) hidden tile for one dataset b, loops h-tiles over H,
// fusing bias+relu+w2-dot into registers so the [T,B,H] intermediate is
// never materialized. Final 16-lane shuffle reduction produces out[t,b].

#define T_DIM 4096
#define B_DIM 8
#define F_DIM 512
#define H_DIM 1024

#define BM 64
#define BN 64
#define BK 32
#define PAD 4

__global__ __launch_bounds__(256, 4)
void mothernet_fused_kernel(const float* __restrict__ x,
                            const float* __restrict__ w1,
                            const float* __restrict__ b1,
                            const float* __restrict__ w2,
                            const float* __restrict__ b2,
                            float* __restrict__ out)
{
    __shared__ float xs[BK][BM + PAD];   // x tile, transposed: [f][t]
    __shared__ float ws[BK][BN + PAD];   // w1 tile: [f][h]

    const int tid = threadIdx.x;
    const int tx  = tid & 15;    // h direction (16 threads x 4 cols = 64)
    const int ty  = tid >> 4;    // t direction (16 threads x 4 rows = 64)
    const int b   = blockIdx.y;
    const int t0  = blockIdx.x * BM;

    const float* xg  = x  + (size_t)t0 * (B_DIM * F_DIM) + (size_t)b * F_DIM;
    const float* w1g = w1 + (size_t)b * (F_DIM * H_DIM);

    float dot[4] = {0.f, 0.f, 0.f, 0.f};   // per-t-row partial of relu(h)·w2

    for (int ht = 0; ht < H_DIM; ht += BN) {
        // hidden accumulators: 4 t-rows x 4 h-cols as 4x2 packed f32x2
        unsigned long long hid[4][2];
        #pragma unroll
        for (int i = 0; i < 4; i++) { hid[i][0] = 0ull; hid[i][1] = 0ull; }

        for (int kt = 0; kt < F_DIM; kt += BK) {
            // ---- load x tile [BM x BK], store transposed as xs[f][t] ----
            #pragma unroll
            for (int q = 0; q < 2; q++) {
                int idx = tid + q * 256;      // 0..511
                int row = idx >> 3;           // t within tile: 0..63
                int c4  = idx & 7;            // f/4 within tile: 0..7
                float4 v = *reinterpret_cast<const float4*>(
                    xg + (size_t)row * (B_DIM * F_DIM) + (kt + c4 * 4));
                // nan_to_num(nan=0)
                v.x = (v.x == v.x) ? v.x : 0.f;
                v.y = (v.y == v.y) ? v.y : 0.f;
                v.z = (v.z == v.z) ? v.z : 0.f;
                v.w = (v.w == v.w) ? v.w : 0.f;
                xs[c4 * 4 + 0][row] = v.x;
                xs[c4 * 4 + 1][row] = v.y;
                xs[c4 * 4 + 2][row] = v.z;
                xs[c4 * 4 + 3][row] = v.w;
            }
            // ---- load w1 tile [BK x BN] ----
            #pragma unroll
            for (int q = 0; q < 2; q++) {
                int idx = tid + q * 256;      // 0..511
                int r  = idx >> 4;            // f within tile: 0..31
                int c4 = idx & 15;            // h/4 within tile: 0..15
                float4 v = *reinterpret_cast<const float4*>(
                    w1g + (size_t)(kt + r) * H_DIM + (ht + c4 * 4));
                *reinterpret_cast<float4*>(&ws[r][c4 * 4]) = v;
            }
            __syncthreads();

            // ---- 64x64x32 microkernel, packed f32x2 FMA ----
            #pragma unroll
            for (int kk = 0; kk < BK; kk++) {
                float4 xv = *reinterpret_cast<const float4*>(&xs[kk][ty * 4]);
                float4 wv = *reinterpret_cast<const float4*>(&ws[kk][tx * 4]);
                unsigned long long w01, w23;
                asm("mov.b64 %0, {%1, %2};" : "=l"(w01) : "f"(wv.x), "f"(wv.y));
                asm("mov.b64 %0, {%1, %2};" : "=l"(w23) : "f"(wv.z), "f"(wv.w));
                float xi[4] = {xv.x, xv.y, xv.z, xv.w};
                #pragma unroll
                for (int i = 0; i < 4; i++) {
                    unsigned long long x2;
                    asm("mov.b64 %0, {%1, %1};" : "=l"(x2) : "f"(xi[i]));
                    asm("fma.rn.f32x2 %0, %1, %2, %0;"
                        : "+l"(hid[i][0]) : "l"(x2), "l"(w01));
                    asm("fma.rn.f32x2 %0, %1, %2, %0;"
                        : "+l"(hid[i][1]) : "l"(x2), "l"(w23));
                }
            }
            __syncthreads();
        }

        // ---- fused epilogue for this h tile: +b1, relu, dot with w2 ----
        float4 b1v = *reinterpret_cast<const float4*>(
            b1 + (size_t)b * H_DIM + ht + tx * 4);
        float4 w2v = *reinterpret_cast<const float4*>(
            w2 + (size_t)b * H_DIM + ht + tx * 4);
        #pragma unroll
        for (int i = 0; i < 4; i++) {
            float h0, h1, h2, h3;
            asm("mov.b64 {%0, %1}, %2;" : "=f"(h0), "=f"(h1) : "l"(hid[i][0]));
            asm("mov.b64 {%0, %1}, %2;" : "=f"(h2), "=f"(h3) : "l"(hid[i][1]));
            h0 = fmaxf(h0 + b1v.x, 0.f);
            h1 = fmaxf(h1 + b1v.y, 0.f);
            h2 = fmaxf(h2 + b1v.z, 0.f);
            h3 = fmaxf(h3 + b1v.w, 0.f);
            dot[i] += h0 * w2v.x + h1 * w2v.y + h2 * w2v.z + h3 * w2v.w;
        }
    }

    // ---- reduce across the 16 tx lanes (same-ty lanes are a contiguous
    //      16-lane group within the warp) and write out ----
    const float b2v = b2[b];
    #pragma unroll
    for (int i = 0; i < 4; i++) {
        float v = dot[i];
        v += __shfl_xor_sync(0xffffffffu, v, 8);
        v += __shfl_xor_sync(0xffffffffu, v, 4);
        v += __shfl_xor_sync(0xffffffffu, v, 2);
        v += __shfl_xor_sync(0xffffffffu, v, 1);
        if (tx == 0) {
            int t = t0 + ty * 4 + i;
            out[(size_t)t * B_DIM + b] = v + b2v;
        }
    }
}

extern "C" void kernel_launch(void* const* d_in, const int* in_sizes, int n_in,
                              void* d_out, int out_size)
{
    (void)in_sizes; (void)n_in; (void)out_size;
    const float* x  = (const float*)d_in[0];   // [T,B,F]
    const float* w1 = (const float*)d_in[1];   // [B,F,H]
    const float* b1 = (const float*)d_in[2];   // [B,H]
    const float* w2 = (const float*)d_in[3];   // [B,H,1]
    const float* b2 = (const float*)d_in[4];   // [B,1]
    float* out = (float*)d_out;                // [T,B,1]

    dim3 grid(T_DIM / BM, B_DIM);
    mothernet_fused_kernel<<<grid, 256>>>(x, w1, b1, w2, b2, out);
}

// round 4
// speedup vs baseline: 1.3803x; 1.3803x over previous
#include <cuda_runtime.h>
#include <cstdint>
#include <cstddef>

// MotherNetRegression fused forward:
//   out[t,b] = relu(x[t,b,:] @ W1[b] + b1[b]) @ w2[b] + b2[b]
// T=4096, B=8, F=512, H=1024, O=1
//
// R3: same 128x128x32 / 8x8-per-thread f32x2 design as R1/R2 (which hit
// container failures twice, never ran), but compile-size de-risked:
// kk loop unrolled 4x instead of 32x, x-broadcast packs hoisted.

#define T_DIM 4096
#define B_DIM 8
#define F_DIM 512
#define H_DIM 1024

#define BM 128
#define BN 128
#define BK 32
#define PAD 4

__global__ __launch_bounds__(256, 2)
void mothernet_fused_kernel(const float* __restrict__ x,
                            const float* __restrict__ w1,
                            const float* __restrict__ b1,
                            const float* __restrict__ w2,
                            const float* __restrict__ b2,
                            float* __restrict__ out)
{
    __shared__ float xs[BK][BM + PAD];   // x tile, transposed: [f][t]
    __shared__ float ws[BK][BN + PAD];   // w1 tile: [f][h]

    const int tid = threadIdx.x;
    const int tx  = tid & 15;    // h direction: cols tx*4 and 64+tx*4
    const int ty  = tid >> 4;    // t direction: rows ty*4 and 64+ty*4
    const int b   = blockIdx.y;
    const int t0  = blockIdx.x * BM;

    const float* xg  = x  + (size_t)t0 * (B_DIM * F_DIM) + (size_t)b * F_DIM;
    const float* w1g = w1 + (size_t)b * (F_DIM * H_DIM);

    float dot[2][4];                      // per t-quadrant, per t-row
    #pragma unroll
    for (int p = 0; p < 2; p++)
        #pragma unroll
        for (int i = 0; i < 4; i++) dot[p][i] = 0.f;

    for (int ht = 0; ht < H_DIM; ht += BN) {
        // hidden accumulators: [t-quad][h-quad][t-row] x 2 packed f32x2
        unsigned long long hid[2][2][4][2];
        #pragma unroll
        for (int p = 0; p < 2; p++)
            #pragma unroll
            for (int q = 0; q < 2; q++)
                #pragma unroll
                for (int i = 0; i < 4; i++) {
                    hid[p][q][i][0] = 0ull;
                    hid[p][q][i][1] = 0ull;
                }

        for (int kt = 0; kt < F_DIM; kt += BK) {
            // ---- load x tile [BM x BK], store transposed as xs[f][t] ----
            #pragma unroll
            for (int qq = 0; qq < 4; qq++) {
                int idx = tid + qq * 256;     // 0..1023
                int row = idx >> 3;           // t within tile: 0..127
                int c4  = idx & 7;            // f/4 within tile: 0..7
                float4 v = *reinterpret_cast<const float4*>(
                    xg + (size_t)row * (B_DIM * F_DIM) + (kt + c4 * 4));
                // nan_to_num(nan=0)
                v.x = (v.x == v.x) ? v.x : 0.f;
                v.y = (v.y == v.y) ? v.y : 0.f;
                v.z = (v.z == v.z) ? v.z : 0.f;
                v.w = (v.w == v.w) ? v.w : 0.f;
                xs[c4 * 4 + 0][row] = v.x;
                xs[c4 * 4 + 1][row] = v.y;
                xs[c4 * 4 + 2][row] = v.z;
                xs[c4 * 4 + 3][row] = v.w;
            }
            // ---- load w1 tile [BK x BN] ----
            #pragma unroll
            for (int qq = 0; qq < 4; qq++) {
                int idx = tid + qq * 256;     // 0..1023
                int r  = idx >> 5;            // f within tile: 0..31
                int c4 = idx & 31;            // h/4 within tile: 0..31
                float4 v = *reinterpret_cast<const float4*>(
                    w1g + (size_t)(kt + r) * H_DIM + (ht + c4 * 4));
                *reinterpret_cast<float4*>(&ws[r][c4 * 4]) = v;
            }
            __syncthreads();

            // ---- 128x128x32 microkernel, 8x8 per thread, f32x2 FMA ----
            #pragma unroll 4
            for (int kk = 0; kk < BK; kk++) {
                float4 xv0 = *reinterpret_cast<const float4*>(&xs[kk][ty * 4]);
                float4 xv1 = *reinterpret_cast<const float4*>(&xs[kk][64 + ty * 4]);
                float4 wv0 = *reinterpret_cast<const float4*>(&ws[kk][tx * 4]);
                float4 wv1 = *reinterpret_cast<const float4*>(&ws[kk][64 + tx * 4]);
                unsigned long long w00, w01, w10, w11;
                asm("mov.b64 %0, {%1, %2};" : "=l"(w00) : "f"(wv0.x), "f"(wv0.y));
                asm("mov.b64 %0, {%1, %2};" : "=l"(w01) : "f"(wv0.z), "f"(wv0.w));
                asm("mov.b64 %0, {%1, %2};" : "=l"(w10) : "f"(wv1.x), "f"(wv1.y));
                asm("mov.b64 %0, {%1, %2};" : "=l"(w11) : "f"(wv1.z), "f"(wv1.w));
                // broadcast-packed x values, hoisted once per kk
                unsigned long long x2[2][4];
                asm("mov.b64 %0, {%1, %1};" : "=l"(x2[0][0]) : "f"(xv0.x));
                asm("mov.b64 %0, {%1, %1};" : "=l"(x2[0][1]) : "f"(xv0.y));
                asm("mov.b64 %0, {%1, %1};" : "=l"(x2[0][2]) : "f"(xv0.z));
                asm("mov.b64 %0, {%1, %1};" : "=l"(x2[0][3]) : "f"(xv0.w));
                asm("mov.b64 %0, {%1, %1};" : "=l"(x2[1][0]) : "f"(xv1.x));
                asm("mov.b64 %0, {%1, %1};" : "=l"(x2[1][1]) : "f"(xv1.y));
                asm("mov.b64 %0, {%1, %1};" : "=l"(x2[1][2]) : "f"(xv1.z));
                asm("mov.b64 %0, {%1, %1};" : "=l"(x2[1][3]) : "f"(xv1.w));
                #pragma unroll
                for (int p = 0; p < 2; p++) {
                    #pragma unroll
                    for (int i = 0; i < 4; i++) {
                        asm("fma.rn.f32x2 %0, %1, %2, %0;"
                            : "+l"(hid[p][0][i][0]) : "l"(x2[p][i]), "l"(w00));
                        asm("fma.rn.f32x2 %0, %1, %2, %0;"
                            : "+l"(hid[p][0][i][1]) : "l"(x2[p][i]), "l"(w01));
                        asm("fma.rn.f32x2 %0, %1, %2, %0;"
                            : "+l"(hid[p][1][i][0]) : "l"(x2[p][i]), "l"(w10));
                        asm("fma.rn.f32x2 %0, %1, %2, %0;"
                            : "+l"(hid[p][1][i][1]) : "l"(x2[p][i]), "l"(w11));
                    }
                }
            }
            __syncthreads();
        }

        // ---- fused epilogue for this h tile: +b1, relu, dot with w2 ----
        #pragma unroll
        for (int q = 0; q < 2; q++) {
            int hcol = ht + q * 64 + tx * 4;
            float4 b1v = *reinterpret_cast<const float4*>(b1 + (size_t)b * H_DIM + hcol);
            float4 w2v = *reinterpret_cast<const float4*>(w2 + (size_t)b * H_DIM + hcol);
            #pragma unroll
            for (int p = 0; p < 2; p++) {
                #pragma unroll
                for (int i = 0; i < 4; i++) {
                    float h0, h1, h2, h3;
                    asm("mov.b64 {%0, %1}, %2;" : "=f"(h0), "=f"(h1) : "l"(hid[p][q][i][0]));
                    asm("mov.b64 {%0, %1}, %2;" : "=f"(h2), "=f"(h3) : "l"(hid[p][q][i][1]));
                    h0 = fmaxf(h0 + b1v.x, 0.f);
                    h1 = fmaxf(h1 + b1v.y, 0.f);
                    h2 = fmaxf(h2 + b1v.z, 0.f);
                    h3 = fmaxf(h3 + b1v.w, 0.f);
                    dot[p][i] += h0 * w2v.x + h1 * w2v.y + h2 * w2v.z + h3 * w2v.w;
                }
            }
        }
    }

    // ---- reduce across the 16 tx lanes and write out ----
    const float b2v = b2[b];
    #pragma unroll
    for (int p = 0; p < 2; p++) {
        #pragma unroll
        for (int i = 0; i < 4; i++) {
            float v = dot[p][i];
            v += __shfl_xor_sync(0xffffffffu, v, 8);
            v += __shfl_xor_sync(0xffffffffu, v, 4);
            v += __shfl_xor_sync(0xffffffffu, v, 2);
            v += __shfl_xor_sync(0xffffffffu, v, 1);
            if (tx == 0) {
                int t = t0 + p * 64 + ty * 4 + i;
                out[(size_t)t * B_DIM + b] = v + b2v;
            }
        }
    }
}

extern "C" void kernel_launch(void* const* d_in, const int* in_sizes, int n_in,
                              void* d_out, int out_size)
{
    (void)in_sizes; (void)n_in; (void)out_size;
    const float* x  = (const float*)d_in[0];   // [T,B,F]
    const float* w1 = (const float*)d_in[1];   // [B,F,H]
    const float* b1 = (const float*)d_in[2];   // [B,H]
    const float* w2 = (const float*)d_in[3];   // [B,H,1]
    const float* b2 = (const float*)d_in[4];   // [B,1]
    float* out = (float*)d_out;                // [T,B,1]

    dim3 grid(T_DIM / BM, B_DIM);
    mothernet_fused_kernel<<<grid, 256>>>(x, w1, b1, w2, b2, out);
}